// round 14
// baseline (speedup 1.0000x reference)
#include <cuda_runtime.h>

// Unpool_LS: 2x2 block learned-sparsity unpool.
// x0: [8,256,256,64] f32, x1: [8,128,128,64] f32
// outputs concatenated into d_out:
//   out0 [8,256,256,64], repl [8,128,128,64], out3 [8,256,256,64]
//
// R13: R11 body (member-name access, FMNMX sorting network, nothing
// address-taken) with two register cuts, then a 6-blocks/SM occupancy target:
//   - frac float4 eliminated: 2-bit kb per lane packed into mask bits 16..23,
//     frac reconstructed from constants at store time (IEEE-identical to
//     (kb+1)/(kb+2) in f32; also deletes 4 FDIVs).
//   - __launch_bounds__(256, 6) -> ptxas targets 40 regs -> 48 warps/SM.

#define BB   8
#define HH   256
#define WW   256
#define CC   64
#define hh2  128
#define ww2  128
#define C4   (CC / 4)   // 16 float4 per position

// Solve one scalar channel (member MEM of the five float4s), in place:
//   a0..a3.MEM <- out0 values, pv.MEM <- repl,
//   mask bits SH..SH+3 <- selection, bits KSH..KSH+1 <- kb.
#define SOLVE(MEM, SH, KSH) do {                                              \
    float v0 = a0.MEM, v1 = a1.MEM, v2 = a2.MEM, v3 = a3.MEM;                 \
    /* stable descending rank (mask only) */                                  \
    int r0 = (int)(v1 >  v0) + (int)(v2 >  v0) + (int)(v3 >  v0);             \
    int r1 = (int)(v0 >= v1) + (int)(v2 >  v1) + (int)(v3 >  v1);             \
    int r2 = (int)(v0 >= v2) + (int)(v1 >= v2) + (int)(v3 >  v2);             \
    int r3 = (int)(v0 >= v3) + (int)(v1 >= v3) + (int)(v2 >= v3);             \
    /* sorted descending via branchless network (FMNMX only) */               \
    float hi01 = fmaxf(v0, v1), lo01 = fminf(v0, v1);                         \
    float hi23 = fmaxf(v2, v3), lo23 = fminf(v2, v3);                         \
    float sv0  = fmaxf(hi01, hi23), mhi = fminf(hi01, hi23);                  \
    float sv3  = fminf(lo01, lo23), mlo = fmaxf(lo01, lo23);                  \
    float sv1  = fmaxf(mhi, mlo),   sv2 = fminf(mhi, mlo);                    \
    /* avg[k] = (prefix+x1)/(k+2); first-max argmax (strict >) */             \
    float x1v  = pv.MEM;                                                      \
    float s    = sv0;                                                         \
    float best = (s + x1v) * 0.5f;  /* /2 == *0.5f, IEEE-identical */         \
    int   kb   = 0;                                                           \
    float avg;                                                                \
    s += sv1; avg = (s + x1v) / 3.0f;  if (avg > best) { best = avg; kb = 1; }\
    s += sv2; avg = (s + x1v) * 0.25f; if (avg > best) { best = avg; kb = 2; }\
    s += sv3; avg = (s + x1v) / 5.0f;  if (avg > best) { best = avg; kb = 3; }\
    pv.MEM = best;                                                            \
    bool m0 = r0 <= kb, m1 = r1 <= kb, m2 = r2 <= kb, m3 = r3 <= kb;          \
    a0.MEM = m0 ? best : v0;                                                  \
    a1.MEM = m1 ? best : v1;                                                  \
    a2.MEM = m2 ? best : v2;                                                  \
    a3.MEM = m3 ? best : v3;                                                  \
    mask |= ((unsigned)m0 | ((unsigned)m1 << 1) |                             \
             ((unsigned)m2 << 2) | ((unsigned)m3 << 3)) << (SH);              \
    mask |= ((unsigned)kb) << (KSH);                                          \
} while (0)

// frac from 2-bit kb: {0.5, 2/3, 0.75, 0.8} — each is the correctly-rounded
// f32 quotient (kb+1)/(kb+2), so bit-identical to the reference computation.
#define FRAC_OF(kb2) \
    (((kb2) & 2u) ? (((kb2) & 1u) ? 0.8f : 0.75f)           \
                  : (((kb2) & 1u) ? (2.0f / 3.0f) : 0.5f))

__global__ void __launch_bounds__(256, 6)
unpool_ls_kernel(const float4 *__restrict__ x0,
                 const float4 *__restrict__ x1,
                 float4 *__restrict__ out0,
                 float4 *__restrict__ out1,
                 float4 *__restrict__ out2) {
    int t = blockIdx.x * blockDim.x + threadIdx.x;   // [0, 131072*16)
    int cq  = t & (C4 - 1);      // channel quad 0..15
    int blk = t >> 4;            // linear (b,h,w) block index, 0..131071

    int w = blk & (ww2 - 1);
    int h = (blk >> 7) & (hh2 - 1);
    int b = blk >> 14;

    int pos = ((b * HH + 2 * h) * WW + 2 * w);       // position index in x0
    int i00 = pos * C4 + cq;
    int i01 = i00 + C4;
    int i10 = i00 + WW * C4;
    int i11 = i10 + C4;
    int ip  = blk * C4 + cq;

    // Front-batched loads (MLP=5)
    float4 a0 = x0[i00];
    float4 a1 = x0[i01];
    float4 a2 = x0[i10];
    float4 a3 = x0[i11];
    float4 pv = x1[ip];

    unsigned mask = 0;   // bits 0..15: replaced; bits 16..23: per-lane kb

    SOLVE(x, 0, 16);
    SOLVE(y, 4, 18);
    SOLVE(z, 8, 20);
    SOLVE(w, 12, 22);

    // out0 (replaced-value map) — inputs overwritten in place
    out0[i00] = a0;
    out0[i01] = a1;
    out0[i10] = a2;
    out0[i11] = a3;

    // repl
    out1[ip] = pv;

    // out3 (fraction map) from mask + reconstructed per-lane frac
    {
        float frx = FRAC_OF((mask >> 16) & 3u);
        float fry = FRAC_OF((mask >> 18) & 3u);
        float frz = FRAC_OF((mask >> 20) & 3u);
        float frw = FRAC_OF((mask >> 22) & 3u);

        float4 f;
        f.x = (mask & 0x0001u) ? frx : 1.0f;
        f.y = (mask & 0x0010u) ? fry : 1.0f;
        f.z = (mask & 0x0100u) ? frz : 1.0f;
        f.w = (mask & 0x1000u) ? frw : 1.0f;
        out2[i00] = f;
        f.x = (mask & 0x0002u) ? frx : 1.0f;
        f.y = (mask & 0x0020u) ? fry : 1.0f;
        f.z = (mask & 0x0200u) ? frz : 1.0f;
        f.w = (mask & 0x2000u) ? frw : 1.0f;
        out2[i01] = f;
        f.x = (mask & 0x0004u) ? frx : 1.0f;
        f.y = (mask & 0x0040u) ? fry : 1.0f;
        f.z = (mask & 0x0400u) ? frz : 1.0f;
        f.w = (mask & 0x4000u) ? frw : 1.0f;
        out2[i10] = f;
        f.x = (mask & 0x0008u) ? frx : 1.0f;
        f.y = (mask & 0x0080u) ? fry : 1.0f;
        f.z = (mask & 0x0800u) ? frz : 1.0f;
        f.w = (mask & 0x8000u) ? frw : 1.0f;
        out2[i11] = f;
    }
}

extern "C" void kernel_launch(void* const* d_in, const int* in_sizes, int n_in,
                              void* d_out, int out_size) {
    const float* x0 = (const float*)d_in[0];
    const float* x1 = (const float*)d_in[1];
    float* out = (float*)d_out;

    const size_t N0 = (size_t)BB * HH * WW * CC;     // 33554432
    const size_t N1 = (size_t)BB * hh2 * ww2 * CC;   // 8388608

    float* out0 = out;
    float* out1 = out + N0;
    float* out2 = out + N0 + N1;

    const int total_threads = (BB * hh2 * ww2) * C4; // 2097152
    const int block = 256;
    const int grid = total_threads / block;          // 8192

    unpool_ls_kernel<<<grid, block>>>((const float4*)x0, (const float4*)x1,
                                      (float4*)out0, (float4*)out1, (float4*)out2);
}

// round 15
// speedup vs baseline: 1.0226x; 1.0226x over previous
#include <cuda_runtime.h>

// Unpool_LS: 2x2 block learned-sparsity unpool.
// x0: [8,256,256,64] f32, x1: [8,128,128,64] f32
// outputs concatenated into d_out:
//   out0 [8,256,256,64], repl [8,128,128,64], out3 [8,256,256,64]
//
// R15: exact R11 body (best codegen: uncapped regs=48, member-name lane access,
// FMNMX sorting network, nothing address-taken) + streaming cache hints as the
// ONLY change. __ldcs/__stcs mark all traffic single-touch/evict-first so L2
// residency and DRAM scheduling favor batched writebacks (448 MB streamed once,
// ~64% writes). Isolates the hint variable that R6 confounded with spills.

#define BB   8
#define HH   256
#define WW   256
#define CC   64
#define hh2  128
#define ww2  128
#define C4   (CC / 4)   // 16 float4 per position

// Solve one scalar channel (member MEM of the five float4s), in place:
//   a0..a3.MEM <- out0 values, pv.MEM <- repl, fr.MEM <- frac, mask bits SH..SH+3.
#define SOLVE(MEM, SH) do {                                                   \
    float v0 = a0.MEM, v1 = a1.MEM, v2 = a2.MEM, v3 = a3.MEM;                 \
    /* stable descending rank (mask only) */                                  \
    int r0 = (int)(v1 >  v0) + (int)(v2 >  v0) + (int)(v3 >  v0);             \
    int r1 = (int)(v0 >= v1) + (int)(v2 >  v1) + (int)(v3 >  v1);             \
    int r2 = (int)(v0 >= v2) + (int)(v1 >= v2) + (int)(v3 >  v2);             \
    int r3 = (int)(v0 >= v3) + (int)(v1 >= v3) + (int)(v2 >= v3);             \
    /* sorted descending via branchless network (FMNMX only) */               \
    float hi01 = fmaxf(v0, v1), lo01 = fminf(v0, v1);                         \
    float hi23 = fmaxf(v2, v3), lo23 = fminf(v2, v3);                         \
    float sv0  = fmaxf(hi01, hi23), mhi = fminf(hi01, hi23);                  \
    float sv3  = fminf(lo01, lo23), mlo = fmaxf(lo01, lo23);                  \
    float sv1  = fmaxf(mhi, mlo),   sv2 = fminf(mhi, mlo);                    \
    /* avg[k] = (prefix+x1)/(k+2); first-max argmax (strict >) */             \
    float x1v  = pv.MEM;                                                      \
    float s    = sv0;                                                         \
    float best = (s + x1v) * 0.5f;  /* /2 == *0.5f, IEEE-identical */         \
    int   kb   = 0;                                                           \
    float avg;                                                                \
    s += sv1; avg = (s + x1v) / 3.0f;  if (avg > best) { best = avg; kb = 1; }\
    s += sv2; avg = (s + x1v) * 0.25f; if (avg > best) { best = avg; kb = 2; }\
    s += sv3; avg = (s + x1v) / 5.0f;  if (avg > best) { best = avg; kb = 3; }\
    pv.MEM = best;                                                            \
    fr.MEM = (float)(kb + 1) / (float)(kb + 2);                               \
    bool m0 = r0 <= kb, m1 = r1 <= kb, m2 = r2 <= kb, m3 = r3 <= kb;          \
    a0.MEM = m0 ? best : v0;                                                  \
    a1.MEM = m1 ? best : v1;                                                  \
    a2.MEM = m2 ? best : v2;                                                  \
    a3.MEM = m3 ? best : v3;                                                  \
    mask |= ((unsigned)m0 | ((unsigned)m1 << 1) |                             \
             ((unsigned)m2 << 2) | ((unsigned)m3 << 3)) << (SH);              \
} while (0)

__global__ void __launch_bounds__(256)
unpool_ls_kernel(const float4 *__restrict__ x0,
                 const float4 *__restrict__ x1,
                 float4 *__restrict__ out0,
                 float4 *__restrict__ out1,
                 float4 *__restrict__ out2) {
    int t = blockIdx.x * blockDim.x + threadIdx.x;   // [0, 131072*16)
    int cq  = t & (C4 - 1);      // channel quad 0..15
    int blk = t >> 4;            // linear (b,h,w) block index, 0..131071

    int w = blk & (ww2 - 1);
    int h = (blk >> 7) & (hh2 - 1);
    int b = blk >> 14;

    int pos = ((b * HH + 2 * h) * WW + 2 * w);       // position index in x0
    int i00 = pos * C4 + cq;
    int i01 = i00 + C4;
    int i10 = i00 + WW * C4;
    int i11 = i10 + C4;
    int ip  = blk * C4 + cq;

    // Front-batched streaming loads (MLP=5, evict-first)
    float4 a0 = __ldcs(&x0[i00]);
    float4 a1 = __ldcs(&x0[i01]);
    float4 a2 = __ldcs(&x0[i10]);
    float4 a3 = __ldcs(&x0[i11]);
    float4 pv = __ldcs(&x1[ip]);

    float4 fr;
    unsigned mask = 0;   // bit (lane*4 + position): replaced

    SOLVE(x, 0);
    SOLVE(y, 4);
    SOLVE(z, 8);
    SOLVE(w, 12);

    // out0 (replaced-value map) — inputs overwritten in place
    __stcs(&out0[i00], a0);
    __stcs(&out0[i01], a1);
    __stcs(&out0[i10], a2);
    __stcs(&out0[i11], a3);

    // repl
    __stcs(&out1[ip], pv);

    // out3 (fraction map) from mask + fr
    {
        float4 f;
        f.x = (mask & 0x0001u) ? fr.x : 1.0f;
        f.y = (mask & 0x0010u) ? fr.y : 1.0f;
        f.z = (mask & 0x0100u) ? fr.z : 1.0f;
        f.w = (mask & 0x1000u) ? fr.w : 1.0f;
        __stcs(&out2[i00], f);
        f.x = (mask & 0x0002u) ? fr.x : 1.0f;
        f.y = (mask & 0x0020u) ? fr.y : 1.0f;
        f.z = (mask & 0x0200u) ? fr.z : 1.0f;
        f.w = (mask & 0x2000u) ? fr.w : 1.0f;
        __stcs(&out2[i01], f);
        f.x = (mask & 0x0004u) ? fr.x : 1.0f;
        f.y = (mask & 0x0040u) ? fr.y : 1.0f;
        f.z = (mask & 0x0400u) ? fr.z : 1.0f;
        f.w = (mask & 0x4000u) ? fr.w : 1.0f;
        __stcs(&out2[i10], f);
        f.x = (mask & 0x0008u) ? fr.x : 1.0f;
        f.y = (mask & 0x0080u) ? fr.y : 1.0f;
        f.z = (mask & 0x0800u) ? fr.z : 1.0f;
        f.w = (mask & 0x8000u) ? fr.w : 1.0f;
        __stcs(&out2[i11], f);
    }
}

extern "C" void kernel_launch(void* const* d_in, const int* in_sizes, int n_in,
                              void* d_out, int out_size) {
    const float* x0 = (const float*)d_in[0];
    const float* x1 = (const float*)d_in[1];
    float* out = (float*)d_out;

    const size_t N0 = (size_t)BB * HH * WW * CC;     // 33554432
    const size_t N1 = (size_t)BB * hh2 * ww2 * CC;   // 8388608

    float* out0 = out;
    float* out1 = out + N0;
    float* out2 = out + N0 + N1;

    const int total_threads = (BB * hh2 * ww2) * C4; // 2097152
    const int block = 256;
    const int grid = total_threads / block;          // 8192

    unpool_ls_kernel<<<grid, block>>>((const float4*)x0, (const float4*)x1,
                                      (float4*)out0, (float4*)out1, (float4*)out2);
}